// round 17
// baseline (speedup 1.0000x reference)
#include <cuda_runtime.h>
#include <cstdint>
#include <cstddef>

// Problem dims
#define BB 16
#define TT 4096
#define DD 512
#define HH 512
#define NC 1536   // 3*H

typedef unsigned long long ull;

// ---------------- scratch (device globals: no runtime allocation allowed) ---
__device__ float g_xk[(size_t)BB * TT * NC];   // 402 MB: x @ kernel + bias0
// Replicated tagged handoff: [parity][group][dstCTA][srcCTA][batch][unit]
__device__ ull   g_hx2[2][8][16][16][2][32];   // 2 MB

// ---------------- f32x2 packed-math helpers (sm_103a) -----------------------
__device__ __forceinline__ ull pk2(float lo, float hi) {
    ull r;
    asm("mov.b64 %0, {%1, %2};" : "=l"(r) : "f"(lo), "f"(hi));
    return r;
}
__device__ __forceinline__ void unpk2(float& lo, float& hi, ull v) {
    asm("mov.b64 {%0, %1}, %2;" : "=f"(lo), "=f"(hi) : "l"(v));
}
__device__ __forceinline__ ull fma2(ull a, ull b, ull c) {
    ull d;
    asm("fma.rn.f32x2 %0, %1, %2, %3;" : "=l"(d) : "l"(a), "l"(b), "l"(c));
    return d;
}
__device__ __forceinline__ float sigmoid_f(float x) {
    return 1.f / (1.f + __expf(-x));
}
__device__ __forceinline__ float tanh_f(float x) {
    float e = __expf(2.f * x);
    return (e - 1.f) / (e + 1.f);
}
__device__ __forceinline__ uint32_t f2tf32(float f) {
    uint32_t r;
    asm("cvt.rna.tf32.f32 %0, %1;" : "=r"(r) : "f"(f));
    return r;
}
__device__ __forceinline__ void mma_tf32(float* c,
                                         uint32_t a0, uint32_t a1,
                                         uint32_t a2, uint32_t a3,
                                         uint32_t b0, uint32_t b1) {
    asm volatile(
        "mma.sync.aligned.m16n8k8.row.col.f32.tf32.tf32.f32 "
        "{%0,%1,%2,%3}, {%4,%5,%6,%7}, {%8,%9}, {%0,%1,%2,%3};"
        : "+f"(c[0]), "+f"(c[1]), "+f"(c[2]), "+f"(c[3])
        : "r"(a0), "r"(a1), "r"(a2), "r"(a3), "r"(b0), "r"(b1));
}

// ============================================================================
// Phase 1: xk = x @ W + bias0  (tf32 tensor cores, unchanged from R12/R16)
// ============================================================================
#define GBM 128
#define GBN 64
#define GBK 32
#define ASTR 36
#define BSTR 68

__global__ void __launch_bounds__(256, 2)
gemm_xk_tf32(const float* __restrict__ A,
             const float* __restrict__ W,
             const float* __restrict__ bias)
{
    __shared__ float As[2][GBM][ASTR];
    __shared__ float Bs[2][GBK][BSTR];

    const int bm   = blockIdx.y * GBM;
    const int bn   = blockIdx.x * GBN;
    const int tid  = threadIdx.x;
    const int wid  = tid >> 5;
    const int lane = tid & 31;
    const int wm   = (wid & 3) * 32;
    const int wn   = (wid >> 2) * 32;
    const int lr   = lane >> 2;
    const int lc   = lane & 3;

    float acc[2][4][4];
#pragma unroll
    for (int mi = 0; mi < 2; mi++)
#pragma unroll
        for (int ni = 0; ni < 4; ni++)
#pragma unroll
            for (int q = 0; q < 4; q++) acc[mi][ni][q] = 0.f;

    float4 aref[4], bref[2];

#pragma unroll
    for (int i = 0; i < 4; i++) {
        int f = tid + i * 256, row = f >> 3, c4 = (f & 7) << 2;
        aref[i] = *(const float4*)&A[(size_t)(bm + row) * DD + c4];
    }
#pragma unroll
    for (int i = 0; i < 2; i++) {
        int f = tid + i * 256, k = f >> 4, n4 = (f & 15) << 2;
        bref[i] = *(const float4*)&W[(size_t)k * NC + bn + n4];
    }
#pragma unroll
    for (int i = 0; i < 4; i++) {
        int f = tid + i * 256, row = f >> 3, c4 = (f & 7) << 2;
        *(float4*)&As[0][row][c4] = aref[i];
    }
#pragma unroll
    for (int i = 0; i < 2; i++) {
        int f = tid + i * 256, k = f >> 4, n4 = (f & 15) << 2;
        *(float4*)&Bs[0][k][n4] = bref[i];
    }
    __syncthreads();

    const int NKT = DD / GBK;
    for (int kt = 0; kt < NKT; kt++) {
        const int cur = kt & 1;

        if (kt < NKT - 1) {
            int kb = (kt + 1) * GBK;
#pragma unroll
            for (int i = 0; i < 4; i++) {
                int f = tid + i * 256, row = f >> 3, c4 = (f & 7) << 2;
                aref[i] = *(const float4*)&A[(size_t)(bm + row) * DD + kb + c4];
            }
#pragma unroll
            for (int i = 0; i < 2; i++) {
                int f = tid + i * 256, k = f >> 4, n4 = (f & 15) << 2;
                bref[i] = *(const float4*)&W[(size_t)(kb + k) * NC + bn + n4];
            }
        }

#pragma unroll
        for (int k8 = 0; k8 < 4; k8++) {
            uint32_t bf[4][2];
#pragma unroll
            for (int ni = 0; ni < 4; ni++) {
                int cb = wn + ni * 8;
                bf[ni][0] = f2tf32(Bs[cur][k8 * 8 + lc    ][cb + lr]);
                bf[ni][1] = f2tf32(Bs[cur][k8 * 8 + lc + 4][cb + lr]);
            }
#pragma unroll
            for (int mi = 0; mi < 2; mi++) {
                int rb = wm + mi * 16;
                uint32_t a0 = f2tf32(As[cur][rb + lr    ][k8 * 8 + lc    ]);
                uint32_t a1 = f2tf32(As[cur][rb + lr + 8][k8 * 8 + lc    ]);
                uint32_t a2 = f2tf32(As[cur][rb + lr    ][k8 * 8 + lc + 4]);
                uint32_t a3 = f2tf32(As[cur][rb + lr + 8][k8 * 8 + lc + 4]);
#pragma unroll
                for (int ni = 0; ni < 4; ni++)
                    mma_tf32(acc[mi][ni], a0, a1, a2, a3, bf[ni][0], bf[ni][1]);
            }
        }

        if (kt < NKT - 1) {
            __syncthreads();
#pragma unroll
            for (int i = 0; i < 4; i++) {
                int f = tid + i * 256, row = f >> 3, c4 = (f & 7) << 2;
                *(float4*)&As[cur ^ 1][row][c4] = aref[i];
            }
#pragma unroll
            for (int i = 0; i < 2; i++) {
                int f = tid + i * 256, k = f >> 4, n4 = (f & 15) << 2;
                *(float4*)&Bs[cur ^ 1][k][n4] = bref[i];
            }
            __syncthreads();
        }
    }

#pragma unroll
    for (int mi = 0; mi < 2; mi++) {
#pragma unroll
        for (int ni = 0; ni < 4; ni++) {
            int r0 = bm + wm + mi * 16 + lr;
            int c0 = bn + wn + ni * 8 + lc * 2;
            float bz0 = bias[c0], bz1 = bias[c0 + 1];
            float2 v0 = make_float2(acc[mi][ni][0] + bz0, acc[mi][ni][1] + bz1);
            float2 v1 = make_float2(acc[mi][ni][2] + bz0, acc[mi][ni][3] + bz1);
            *(float2*)&g_xk[(size_t)r0 * NC + c0]       = v0;
            *(float2*)&g_xk[(size_t)(r0 + 8) * NC + c0] = v1;
        }
    }
}

// ============================================================================
// Phase 2: persistent GRU recurrence — TAGGED-WORD handoff + PER-CONSUMER
// REPLICATION (removes cross-CTA poll-line contention).
//   8 groups x 16 CTAs; CTA c owns units [32c,32c+32); thread (u=lane,
//   ks=warp) holds U[k0..k0+32) for unit u's 3 gate columns (48 f32x2 regs).
//   Producer gate thread packs {tag=t+1, h' bits} in ONE 8-byte word and
//   stores it 16x (one coalesced st.relaxed.b64 per consumer CTA) into
//   g_hx2[par][g][dst][c][b][u]. Consumer warp ks of CTA c polls ITS PRIVATE
//   region g_hx2[par][g][c][ks][.][u] — 32 lanes of exactly one warp per L2
//   line, zero cross-CTA contention. Single-copy atomicity of the b64 word
//   makes the payload valid the instant the tag matches; no fences/counters.
//   red[] parity double-buffered (racing consumers write red[par^1], then
//   block at the next __syncthreads). Parity-slot reuse safe: a tag t+3
//   overwrite requires the polling warp itself to have passed poll(t).
//   Tags monotonic per replay; 2 MB memset resets them.
// ============================================================================
__global__ void __launch_bounds__(512, 1)
gru_rec_kernel(const float* __restrict__ RK,
               const float* __restrict__ bias,
               float* __restrict__ out)
{
    __shared__ float red[2][16][32][7];    // [parity][ks][u][gate*2+b]
    __shared__ float h_chunk[16][2][32];   // per-warp private h slice
    __shared__ float rb_s[96];             // recurrent bias slice

    const int bx  = blockIdx.x;
    const int g   = bx >> 4;               // group 0..7
    const int c   = bx & 15;               // cta-in-group 0..15
    const int tid = threadIdx.x;
    const int u   = tid & 31;              // lane
    const int ks  = tid >> 5;              // warp / K-split 0..15
    const int jb  = c * 32;                // first unit owned
    const int b0  = g * 2;                 // first global batch
    const int k0  = ks * 32;               // this warp's K chunk

    // ---- Load U slice into registers ---------------------------------------
    ull ureg[3][16];
#pragma unroll
    for (int gi = 0; gi < 3; gi++)
#pragma unroll
        for (int i = 0; i < 16; i++) {
            int k = k0 + 2 * i;
            float lo = RK[(size_t)k       * NC + gi * HH + jb + u];
            float hi = RK[(size_t)(k + 1) * NC + gi * HH + jb + u];
            ureg[gi][i] = pk2(lo, hi);
        }
    if (tid < 96)
        rb_s[tid] = bias[NC + (tid >> 5) * HH + jb + (tid & 31)];
    // zero own h chunk (h0 = 0)
    for (int i = u; i < 64; i += 32) ((float*)h_chunk[ks])[i] = 0.f;
    __syncthreads();

    // consumer: private poll region, parity 0 base
    const ull* pollA0 = &g_hx2[0][g][c][ks][0][u];   // batch 0 word
    const ull* pollB0 = &g_hx2[0][g][c][ks][1][u];   // batch 1 word
    const size_t PAR_STRIDE = (size_t)8 * 16 * 16 * 2 * 32;  // ull elems

    // producer: base of its replicated slots (parity 0, dst 0)
    ull* pub0 = &g_hx2[0][g][0][c][0][u];            // [dst] stride below
    const size_t DST_STRIDE = (size_t)16 * 2 * 32;   // 1024 ull between dsts

    float h_old = 0.f;                     // gate threads: own h from last step

    // xk prefetch for t = 0 (gate warps only)
    float xz = 0.f, xr = 0.f, xh = 0.f;
    size_t xbase0 = 0;
    if (ks < 2) {
        xbase0 = ((size_t)(b0 + ks) * TT) * NC + jb + u;
        xz = g_xk[xbase0];
        xr = g_xk[xbase0 + HH];
        xh = g_xk[xbase0 + 2 * HH];
    }

    for (int t = 0; t < TT; t++) {
        const int par = t & 1;

        // ---- packed dot over own 32-wide K chunk ---------------------------
        const ull* hp0 = (const ull*)h_chunk[ks][0];
        const ull* hp1 = (const ull*)h_chunk[ks][1];
        ull a0 = 0, a1 = 0, a2 = 0, a3 = 0, a4 = 0, a5 = 0;
#pragma unroll
        for (int i = 0; i < 16; i++) {
            ull h0 = hp0[i];               // broadcast LDS.64
            ull h1 = hp1[i];
            a0 = fma2(ureg[0][i], h0, a0);
            a1 = fma2(ureg[1][i], h0, a1);
            a2 = fma2(ureg[2][i], h0, a2);
            a3 = fma2(ureg[0][i], h1, a3);
            a4 = fma2(ureg[1][i], h1, a4);
            a5 = fma2(ureg[2][i], h1, a5);
        }
        {
            float lo, hi;
            unpk2(lo, hi, a0); red[par][ks][u][0] = lo + hi;   // z, b0
            unpk2(lo, hi, a1); red[par][ks][u][2] = lo + hi;   // r, b0
            unpk2(lo, hi, a2); red[par][ks][u][4] = lo + hi;   // h, b0
            unpk2(lo, hi, a3); red[par][ks][u][1] = lo + hi;   // z, b1
            unpk2(lo, hi, a4); red[par][ks][u][3] = lo + hi;   // r, b1
            unpk2(lo, hi, a5); red[par][ks][u][5] = lo + hi;   // h, b1
        }
        __syncthreads();

        // ---- gate warps: reduce + gates + replicated tagged publish --------
        if (ks < 2) {
            float s0 = 0.f, s1 = 0.f, s2 = 0.f;
#pragma unroll
            for (int q = 0; q < 16; q++) {
                s0 += red[par][q][u][0 + ks];
                s1 += red[par][q][u][2 + ks];
                s2 += red[par][q][u][4 + ks];
            }
            s0 += rb_s[u];
            s1 += rb_s[32 + u];
            s2 += rb_s[64 + u];

            float z    = sigmoid_f(xz + s0);
            float r    = sigmoid_f(xr + s1);
            float cand = tanh_f(xh + r * s2);
            float hn   = z * h_old + (1.f - z) * cand;
            h_old = hn;

            int gb = b0 + ks;
            // tagged word: {tag = t+1 (hi32), h' bits (lo32)} — one atom.
            // Replicate to all 16 consumer CTAs (coalesced per instruction).
            {
                ull w = ((ull)(uint32_t)(t + 1) << 32) |
                        (ull)__float_as_uint(hn);
                ull* base = pub0 + ((t + 1) & 1) * PAR_STRIDE
                                 + (size_t)ks * 32;   // [b=ks] sub-slot
#pragma unroll
                for (int dst = 0; dst < 16; dst++)
                    asm volatile("st.relaxed.gpu.global.b64 [%0], %1;"
                                 :: "l"(base + (size_t)dst * DST_STRIDE),
                                    "l"(w) : "memory");
            }
            out[((size_t)gb * TT + t) * HH + jb + u] = hn;
            if (t == TT - 1)
                out[(size_t)BB * TT * HH + (size_t)gb * HH + jb + u] = hn;

            // prefetch next step's xk (consumed next iteration)
            {
                size_t nb = xbase0 + (size_t)((t + 1 < TT) ? t + 1 : t) * NC;
                xz = g_xk[nb];
                xr = g_xk[nb + HH];
                xh = g_xk[nb + 2 * HH];
            }
        }

        // ---- poll own PRIVATE tagged words ---------------------------------
        {
            const ull* pa = pollA0 + ((t + 1) & 1) * PAR_STRIDE;
            const ull* pb = pollB0 + ((t + 1) & 1) * PAR_STRIDE;
            const uint32_t want = (uint32_t)(t + 1);
            ull wa, wb;
            uint32_t ta, tb;
            do {
                asm volatile("ld.relaxed.gpu.global.b64 %0, [%1];"
                             : "=l"(wa) : "l"(pa) : "memory");
                asm volatile("ld.relaxed.gpu.global.b64 %0, [%1];"
                             : "=l"(wb) : "l"(pb) : "memory");
                ta = (uint32_t)(wa >> 32);
                tb = (uint32_t)(wb >> 32);
            } while (ta != want || tb != want);
            h_chunk[ks][0][u] = __uint_as_float((uint32_t)wa);
            h_chunk[ks][1][u] = __uint_as_float((uint32_t)wb);
        }
        __syncwarp();
    }
}

// ============================================================================
extern "C" void kernel_launch(void* const* d_in, const int* in_sizes, int n_in,
                              void* d_out, int out_size)
{
    const float* x    = (const float*)d_in[0];   // [16,4096,512]
    const float* Wk   = (const float*)d_in[1];   // [512,1536]
    const float* RK   = (const float*)d_in[2];   // [512,1536]
    const float* bias = (const float*)d_in[3];   // [2,1536]
    float* out = (float*)d_out;                  // outputs ++ state

    // Reset the tagged words (tags monotonic within a replay; 2 MB memset).
    void* hx_ptr = nullptr;
    cudaGetSymbolAddress(&hx_ptr, g_hx2);
    cudaMemsetAsync(hx_ptr, 0, sizeof(ull) * 2 * 8 * 16 * 16 * 2 * 32);

    // Phase 1: input projection GEMM (tf32 tensor cores).
    dim3 grid1(NC / GBN, (BB * TT) / GBM);
    gemm_xk_tf32<<<grid1, 256>>>(x, Wk, bias);

    // Phase 2: persistent recurrence (tagged words, per-consumer replication).
    gru_rec_kernel<<<128, 512>>>(RK, bias, out);
}